// round 1
// baseline (speedup 1.0000x reference)
#include <cuda_runtime.h>
#include <math.h>

// Problem constants
#define NN 1024   // batch
#define SS 8      // streams
#define II 128    // input dim per stream
#define FF 1024   // hidden dim per stream
#define MM 512    // output dim per stream

// Scratch for h = o * tanh(i*g), layout [S][N][F] (32 MB)
__device__ float g_h[(size_t)SS * NN * FF];

__device__ __forceinline__ float sigmoidf_(float v) {
    return 1.0f / (1.0f + __expf(-v));
}

// ---------------------------------------------------------------------------
// Kernel A: fused 3-gate grouped GEMM + LSTM nonlinearity.
// Per s: C_gate[n,f] = sum_k x[n, s*II + k] * W[s, f, k]  (K = 128)
// h[s,n,f] = sigmoid(po) * tanh( sigmoid(pi) * tanh(pg) )
// Tiles: BM=64 (n), BN=64 (f), BK=32. 256 threads, 4x4 microtile per gate.
// ---------------------------------------------------------------------------
__global__ __launch_bounds__(256) void gates_kernel(
    const float* __restrict__ x,
    const float* __restrict__ Wxi, const float* __restrict__ bi,
    const float* __restrict__ Wxg, const float* __restrict__ bg,
    const float* __restrict__ Wxo, const float* __restrict__ bo)
{
    constexpr int BM = 64, BN = 64, BK = 32;
    __shared__ float As [BK][BM + 1];
    __shared__ float Bi_[BK][BN + 1];
    __shared__ float Bg_[BK][BN + 1];
    __shared__ float Bo_[BK][BN + 1];

    const int s  = blockIdx.z;
    const int n0 = blockIdx.x * BM;
    const int f0 = blockIdx.y * BN;

    const int tid = threadIdx.x;
    const int tx = tid & 15;        // 0..15 -> f microtile
    const int ty = tid >> 4;        // 0..15 -> n microtile

    const int lrow = tid >> 3;          // 0..31  (tile row for loads)
    const int lk   = (tid & 7) << 2;    // 0,4,...,28 (k offset, float4)

    const float* Wi = Wxi + (size_t)s * FF * II;
    const float* Wg = Wxg + (size_t)s * FF * II;
    const float* Wo = Wxo + (size_t)s * FF * II;

    float ai[4][4], ag[4][4], ao[4][4];
#pragma unroll
    for (int i = 0; i < 4; i++)
#pragma unroll
        for (int j = 0; j < 4; j++) { ai[i][j] = 0.f; ag[i][j] = 0.f; ao[i][j] = 0.f; }

    for (int k0 = 0; k0 < II; k0 += BK) {
        // Load A tile (x), transposed into smem: As[k][n]
#pragma unroll
        for (int r = 0; r < BM; r += 32) {
            float4 v = *(const float4*)(x + (size_t)(n0 + lrow + r) * (SS * II)
                                          + s * II + k0 + lk);
            As[lk + 0][lrow + r] = v.x;
            As[lk + 1][lrow + r] = v.y;
            As[lk + 2][lrow + r] = v.z;
            As[lk + 3][lrow + r] = v.w;
        }
        // Load the three gate-weight tiles, transposed: B[k][f]
#pragma unroll
        for (int r = 0; r < BN; r += 32) {
            size_t off = (size_t)(f0 + lrow + r) * II + k0 + lk;
            float4 vi = *(const float4*)(Wi + off);
            Bi_[lk + 0][lrow + r] = vi.x;
            Bi_[lk + 1][lrow + r] = vi.y;
            Bi_[lk + 2][lrow + r] = vi.z;
            Bi_[lk + 3][lrow + r] = vi.w;
            float4 vg = *(const float4*)(Wg + off);
            Bg_[lk + 0][lrow + r] = vg.x;
            Bg_[lk + 1][lrow + r] = vg.y;
            Bg_[lk + 2][lrow + r] = vg.z;
            Bg_[lk + 3][lrow + r] = vg.w;
            float4 vo = *(const float4*)(Wo + off);
            Bo_[lk + 0][lrow + r] = vo.x;
            Bo_[lk + 1][lrow + r] = vo.y;
            Bo_[lk + 2][lrow + r] = vo.z;
            Bo_[lk + 3][lrow + r] = vo.w;
        }
        __syncthreads();

#pragma unroll
        for (int kk = 0; kk < BK; kk++) {
            float a[4], pi[4], pg[4], po[4];
#pragma unroll
            for (int i = 0; i < 4; i++) a[i] = As[kk][ty * 4 + i];
#pragma unroll
            for (int j = 0; j < 4; j++) {
                pi[j] = Bi_[kk][tx * 4 + j];
                pg[j] = Bg_[kk][tx * 4 + j];
                po[j] = Bo_[kk][tx * 4 + j];
            }
#pragma unroll
            for (int i = 0; i < 4; i++)
#pragma unroll
                for (int j = 0; j < 4; j++) {
                    ai[i][j] = fmaf(a[i], pi[j], ai[i][j]);
                    ag[i][j] = fmaf(a[i], pg[j], ag[i][j]);
                    ao[i][j] = fmaf(a[i], po[j], ao[i][j]);
                }
        }
        __syncthreads();
    }

    // Epilogue: biases + LSTM nonlinearity (c0 = 0 -> c = i*g), write h
    const float* bip = bi + (size_t)s * FF + f0 + tx * 4;
    const float* bgp = bg + (size_t)s * FF + f0 + tx * 4;
    const float* bop = bo + (size_t)s * FF + f0 + tx * 4;
    float4 bi4 = *(const float4*)bip;
    float4 bg4 = *(const float4*)bgp;
    float4 bo4 = *(const float4*)bop;
    const float bia[4] = {bi4.x, bi4.y, bi4.z, bi4.w};
    const float bga[4] = {bg4.x, bg4.y, bg4.z, bg4.w};
    const float boa[4] = {bo4.x, bo4.y, bo4.z, bo4.w};

#pragma unroll
    for (int i = 0; i < 4; i++) {
        const int n = n0 + ty * 4 + i;
        float4 hv;
        float* hvp = (float*)&hv;
#pragma unroll
        for (int j = 0; j < 4; j++) {
            float gi = sigmoidf_(ai[i][j] + bia[j]);
            float gg = tanhf(ag[i][j] + bga[j]);
            float go = sigmoidf_(ao[i][j] + boa[j]);
            hvp[j] = go * tanhf(gi * gg);
        }
        *(float4*)(g_h + ((size_t)s * NN + n) * FF + f0 + tx * 4) = hv;
    }
}

// ---------------------------------------------------------------------------
// Kernel B: grouped output GEMM.
// Per s: out[n, s*MM + m] = sum_f h[s,n,f] * Wout[s,m,f] + bout[s,m]
// Tiles: BM=64 (n), BN=64 (m), BK=32. 256 threads, 4x4 microtile.
// ---------------------------------------------------------------------------
__global__ __launch_bounds__(256) void out_kernel(
    const float* __restrict__ Wout, const float* __restrict__ bout,
    float* __restrict__ out)
{
    constexpr int BM = 64, BN = 64, BK = 32;
    __shared__ float As[BK][BM + 1];
    __shared__ float Bs[BK][BN + 1];

    const int s  = blockIdx.z;
    const int n0 = blockIdx.x * BM;
    const int m0 = blockIdx.y * BN;

    const int tid = threadIdx.x;
    const int tx = tid & 15;
    const int ty = tid >> 4;
    const int lrow = tid >> 3;
    const int lk   = (tid & 7) << 2;

    const float* A = g_h  + (size_t)s * NN * FF;
    const float* B = Wout + (size_t)s * MM * FF;

    float acc[4][4];
#pragma unroll
    for (int i = 0; i < 4; i++)
#pragma unroll
        for (int j = 0; j < 4; j++) acc[i][j] = 0.f;

    for (int k0 = 0; k0 < FF; k0 += BK) {
#pragma unroll
        for (int r = 0; r < BM; r += 32) {
            float4 v = *(const float4*)(A + (size_t)(n0 + lrow + r) * FF + k0 + lk);
            As[lk + 0][lrow + r] = v.x;
            As[lk + 1][lrow + r] = v.y;
            As[lk + 2][lrow + r] = v.z;
            As[lk + 3][lrow + r] = v.w;
        }
#pragma unroll
        for (int r = 0; r < BN; r += 32) {
            float4 w = *(const float4*)(B + (size_t)(m0 + lrow + r) * FF + k0 + lk);
            Bs[lk + 0][lrow + r] = w.x;
            Bs[lk + 1][lrow + r] = w.y;
            Bs[lk + 2][lrow + r] = w.z;
            Bs[lk + 3][lrow + r] = w.w;
        }
        __syncthreads();

#pragma unroll
        for (int kk = 0; kk < BK; kk++) {
            float a[4], b[4];
#pragma unroll
            for (int i = 0; i < 4; i++) a[i] = As[kk][ty * 4 + i];
#pragma unroll
            for (int j = 0; j < 4; j++) b[j] = Bs[kk][tx * 4 + j];
#pragma unroll
            for (int i = 0; i < 4; i++)
#pragma unroll
                for (int j = 0; j < 4; j++)
                    acc[i][j] = fmaf(a[i], b[j], acc[i][j]);
        }
        __syncthreads();
    }

    float4 b4 = *(const float4*)(bout + (size_t)s * MM + m0 + tx * 4);
    const float ba[4] = {b4.x, b4.y, b4.z, b4.w};

#pragma unroll
    for (int i = 0; i < 4; i++) {
        const int n = n0 + ty * 4 + i;
        float4 ov;
        float* ovp = (float*)&ov;
#pragma unroll
        for (int j = 0; j < 4; j++) ovp[j] = acc[i][j] + ba[j];
        *(float4*)(out + (size_t)n * (SS * MM) + s * MM + m0 + tx * 4) = ov;
    }
}

// ---------------------------------------------------------------------------
// Launch. Input order (metadata): modulation, Wxi, Whi, bi, Wxf, Whf, bf,
// Wxg, Whg, bg, Wxo, Who, bo, Wout, bout.
// Wh* are multiplied by h0 = 0 and the entire forget gate multiplies c0 = 0,
// so Whi/Wxf/Whf/bf/Whg/Who are dead and never read.
// ---------------------------------------------------------------------------
extern "C" void kernel_launch(void* const* d_in, const int* in_sizes, int n_in,
                              void* d_out, int out_size) {
    const float* mod  = (const float*)d_in[0];
    const float* Wxi  = (const float*)d_in[1];
    const float* bi   = (const float*)d_in[3];
    const float* Wxg  = (const float*)d_in[7];
    const float* bg   = (const float*)d_in[9];
    const float* Wxo  = (const float*)d_in[10];
    const float* bo   = (const float*)d_in[12];
    const float* Wout = (const float*)d_in[13];
    const float* bout = (const float*)d_in[14];
    float* out = (float*)d_out;

    dim3 gridA(NN / 64, FF / 64, SS);   // (16, 16, 8)
    dim3 gridB(NN / 64, MM / 64, SS);   // (16, 8, 8)
    gates_kernel<<<gridA, 256>>>(mod, Wxi, bi, Wxg, bg, Wxo, bo);
    out_kernel<<<gridB, 256>>>(Wout, bout, out);
}

// round 3
// speedup vs baseline: 2.3564x; 2.3564x over previous
#include <cuda_runtime.h>
#include <cuda_bf16.h>
#include <cstdint>
#include <math.h>

#define NN 1024
#define SS 8
#define II 128
#define FF 1024
#define MM 512

// ---------------------------------------------------------------------------
// Scratch (device globals; allocation-free). bf16 hi/lo split copies.
// ---------------------------------------------------------------------------
__device__ __align__(16) __nv_bfloat16 g_xh[SS * NN * II];
__device__ __align__(16) __nv_bfloat16 g_xl[SS * NN * II];
__device__ __align__(16) __nv_bfloat16 g_wih[SS * FF * II];
__device__ __align__(16) __nv_bfloat16 g_wil[SS * FF * II];
__device__ __align__(16) __nv_bfloat16 g_wgh[SS * FF * II];
__device__ __align__(16) __nv_bfloat16 g_wgl[SS * FF * II];
__device__ __align__(16) __nv_bfloat16 g_woh[SS * FF * II];
__device__ __align__(16) __nv_bfloat16 g_wol[SS * FF * II];
__device__ __align__(16) __nv_bfloat16 g_wouth[SS * MM * FF];
__device__ __align__(16) __nv_bfloat16 g_woutl[SS * MM * FF];
__device__ __align__(16) __nv_bfloat16 g_hh[SS * NN * FF];
__device__ __align__(16) __nv_bfloat16 g_hl[SS * NN * FF];

// ---------------------------------------------------------------------------
// Helpers
// ---------------------------------------------------------------------------
__device__ __forceinline__ uint32_t smem_u32(const void* p) {
    uint32_t a;
    asm("{ .reg .u64 t; cvta.to.shared.u64 t, %1; cvt.u32.u64 %0, t; }"
        : "=r"(a) : "l"(p));
    return a;
}

__device__ __forceinline__ void ldsm4(uint32_t* r, uint32_t a) {
    asm volatile("ldmatrix.sync.aligned.m8n8.x4.shared.b16 {%0,%1,%2,%3}, [%4];"
        : "=r"(r[0]), "=r"(r[1]), "=r"(r[2]), "=r"(r[3]) : "r"(a));
}

__device__ __forceinline__ void mma_bf16(float* d, const uint32_t* a,
                                         uint32_t b0, uint32_t b1) {
    asm volatile(
        "mma.sync.aligned.m16n8k16.row.col.f32.bf16.bf16.f32 "
        "{%0,%1,%2,%3}, {%4,%5,%6,%7}, {%8,%9}, {%0,%1,%2,%3};"
        : "+f"(d[0]), "+f"(d[1]), "+f"(d[2]), "+f"(d[3])
        : "r"(a[0]), "r"(a[1]), "r"(a[2]), "r"(a[3]), "r"(b0), "r"(b1));
}

__device__ __forceinline__ void split1(float v, __nv_bfloat16& h, __nv_bfloat16& l) {
    h = __float2bfloat16(v);
    l = __float2bfloat16(v - __bfloat162float(h));
}

// ---------------------------------------------------------------------------
// Convert: fp32 -> bf16 hi/lo. x remapped [N][S][I] -> [S][N][I].
// ---------------------------------------------------------------------------
__global__ __launch_bounds__(256) void convert_all(
    const float* __restrict__ mod, const float* __restrict__ Wxi,
    const float* __restrict__ Wxg, const float* __restrict__ Wxo,
    const float* __restrict__ Wout)
{
    const int i = blockIdx.x * 256 + threadIdx.x;
    const float* src;
    __nv_bfloat16 *dh, *dl;
    size_t soff, doff;

    if (i < 262144) {                       // x remap
        int j = i;
        int i4 = j & 31, n = (j >> 5) & 1023, s = j >> 15;
        src = mod; soff = (size_t)n * (SS * II) + s * II + i4 * 4;
        dh = g_xh; dl = g_xl; doff = ((size_t)s * NN + n) * II + i4 * 4;
    } else if (i < 524288) {                // Wxi
        size_t j = (size_t)(i - 262144) * 4;
        src = Wxi; soff = j; dh = g_wih; dl = g_wil; doff = j;
    } else if (i < 786432) {                // Wxg
        size_t j = (size_t)(i - 524288) * 4;
        src = Wxg; soff = j; dh = g_wgh; dl = g_wgl; doff = j;
    } else if (i < 1048576) {               // Wxo
        size_t j = (size_t)(i - 786432) * 4;
        src = Wxo; soff = j; dh = g_woh; dl = g_wol; doff = j;
    } else {                                // Wout
        size_t j = (size_t)(i - 1048576) * 4;
        src = Wout; soff = j; dh = g_wouth; dl = g_woutl; doff = j;
    }

    float4 v = *(const float4*)(src + soff);
    __nv_bfloat16 h[4], l[4];
    split1(v.x, h[0], l[0]);
    split1(v.y, h[1], l[1]);
    split1(v.z, h[2], l[2]);
    split1(v.w, h[3], l[3]);
    *(uint2*)(dh + doff) = *(uint2*)h;
    *(uint2*)(dl + doff) = *(uint2*)l;
}

// ---------------------------------------------------------------------------
// Gates kernel: CTA tile 128(n) x 64(f) for all 3 gates, K=128 in smem once.
// mma.sync bf16 split (AhBh + AhBl + AlBh). Fused LSTM epilogue -> h hi/lo.
// grid (8, 16, 8), 256 threads (8 warps, 4x2), smem 174080 B.
// ---------------------------------------------------------------------------
__global__ __launch_bounds__(256, 1) void gates_mma(
    const float* __restrict__ bi, const float* __restrict__ bg,
    const float* __restrict__ bo)
{
    extern __shared__ __nv_bfloat16 sm[];
    constexpr int PAD = 136;                // padded k-stride (bf16 elems)
    const int tid = threadIdx.x, wid = tid >> 5, lane = tid & 31;
    const int s = blockIdx.z, n0 = blockIdx.x * 128, f0 = blockIdx.y * 64;

    __nv_bfloat16* Ah = sm;                 // 128 x PAD
    __nv_bfloat16* Al = sm + 128 * PAD;
    __nv_bfloat16* Bbase = sm + 2 * 128 * PAD;  // per gate: hi 64xPAD, lo 64xPAD

    // ---- fill A (x hi/lo) ----
    {
        const __nv_bfloat16* sh = g_xh + ((size_t)s * NN + n0) * II;
        const __nv_bfloat16* sl = g_xl + ((size_t)s * NN + n0) * II;
#pragma unroll
        for (int it = 0; it < 8; it++) {
            int idx = tid + it * 256;
            int row = idx >> 4, q = idx & 15;
            *(uint4*)(Ah + row * PAD + q * 8) =
                *(const uint4*)(sh + (size_t)row * II + q * 8);
            *(uint4*)(Al + row * PAD + q * 8) =
                *(const uint4*)(sl + (size_t)row * II + q * 8);
        }
    }
    // ---- fill B (3 gate weights hi/lo) ----
    const __nv_bfloat16* WH[3] = {g_wih, g_wgh, g_woh};
    const __nv_bfloat16* WL[3] = {g_wil, g_wgl, g_wol};
#pragma unroll
    for (int g = 0; g < 3; g++) {
        const __nv_bfloat16* sh = WH[g] + ((size_t)s * FF + f0) * II;
        const __nv_bfloat16* sl = WL[g] + ((size_t)s * FF + f0) * II;
        __nv_bfloat16* dh = Bbase + g * 2 * 64 * PAD;
        __nv_bfloat16* dl = dh + 64 * PAD;
#pragma unroll
        for (int it = 0; it < 4; it++) {
            int idx = tid + it * 256;
            int row = idx >> 4, q = idx & 15;
            *(uint4*)(dh + row * PAD + q * 8) =
                *(const uint4*)(sh + (size_t)row * II + q * 8);
            *(uint4*)(dl + row * PAD + q * 8) =
                *(const uint4*)(sl + (size_t)row * II + q * 8);
        }
    }
    __syncthreads();

    const int wm = wid & 3, wn = wid >> 2;
    const uint32_t sb = smem_u32(sm);
    const int lrA = lane & 15, lcA = (lane >> 4) << 3;
    const int lrB = ((lane >> 4) << 3) + (lane & 7), lcB = ((lane >> 3) & 1) << 3;

    float acc[3][2][4][4];
#pragma unroll
    for (int g = 0; g < 3; g++)
#pragma unroll
        for (int mb = 0; mb < 2; mb++)
#pragma unroll
            for (int nb = 0; nb < 4; nb++)
#pragma unroll
                for (int e = 0; e < 4; e++) acc[g][mb][nb][e] = 0.f;

    const uint32_t aAh = sb + 2 * ((wm * 32 + lrA) * PAD + lcA);
    const uint32_t aAl = aAh + 2 * (128 * PAD);

#pragma unroll
    for (int kk = 0; kk < 8; kk++) {
        const int k0 = kk * 16;
        uint32_t ah[2][4], al[2][4];
        ldsm4(ah[0], aAh + 2 * k0);
        ldsm4(ah[1], aAh + 2 * (16 * PAD + k0));
        ldsm4(al[0], aAl + 2 * k0);
        ldsm4(al[1], aAl + 2 * (16 * PAD + k0));
#pragma unroll
        for (int g = 0; g < 3; g++) {
            uint32_t bh[2][4], bl[2][4];
            const uint32_t bgb = sb + 2 * (2 * 128 * PAD + g * 2 * 64 * PAD
                                 + (wn * 32 + lrB) * PAD + k0 + lcB);
#pragma unroll
            for (int p = 0; p < 2; p++) {
                ldsm4(bh[p], bgb + 2 * (p * 16 * PAD));
                ldsm4(bl[p], bgb + 2 * (64 * PAD + p * 16 * PAD));
            }
#pragma unroll
            for (int mb = 0; mb < 2; mb++)
#pragma unroll
                for (int nb = 0; nb < 4; nb++) {
                    uint32_t h0 = bh[nb >> 1][(nb & 1) * 2];
                    uint32_t h1 = bh[nb >> 1][(nb & 1) * 2 + 1];
                    uint32_t l0 = bl[nb >> 1][(nb & 1) * 2];
                    uint32_t l1 = bl[nb >> 1][(nb & 1) * 2 + 1];
                    mma_bf16(acc[g][mb][nb], ah[mb], h0, h1);
                    mma_bf16(acc[g][mb][nb], ah[mb], l0, l1);
                    mma_bf16(acc[g][mb][nb], al[mb], h0, h1);
                }
        }
    }

    // ---- fused LSTM epilogue: h = sigm(o) * tanh( sigm(i) * tanh(g) ) ----
#pragma unroll
    for (int nb = 0; nb < 4; nb++) {
        const int fc = f0 + wn * 32 + nb * 8 + (lane & 3) * 2;
        const float bi0 = bi[(size_t)s * FF + fc], bi1 = bi[(size_t)s * FF + fc + 1];
        const float bg0 = bg[(size_t)s * FF + fc], bg1 = bg[(size_t)s * FF + fc + 1];
        const float bo0 = bo[(size_t)s * FF + fc], bo1 = bo[(size_t)s * FF + fc + 1];
#pragma unroll
        for (int mb = 0; mb < 2; mb++)
#pragma unroll
            for (int hf = 0; hf < 2; hf++) {
                const int n = n0 + wm * 32 + mb * 16 + (lane >> 2) + hf * 8;
                const size_t off = ((size_t)s * NN + n) * FF + fc;
                float h2[2];
#pragma unroll
                for (int e = 0; e < 2; e++) {
                    float pi = acc[0][mb][nb][hf * 2 + e] + (e ? bi1 : bi0);
                    float pg = acc[1][mb][nb][hf * 2 + e] + (e ? bg1 : bg0);
                    float po = acc[2][mb][nb][hf * 2 + e] + (e ? bo1 : bo0);
                    float iv = 1.f / (1.f + __expf(-pi));
                    float gv = tanhf(pg);
                    float ov = 1.f / (1.f + __expf(-po));
                    h2[e] = ov * tanhf(iv * gv);
                }
                __nv_bfloat162 vh, vl;
                split1(h2[0], vh.x, vl.x);
                split1(h2[1], vh.y, vl.y);
                *(__nv_bfloat162*)(g_hh + off) = vh;
                *(__nv_bfloat162*)(g_hl + off) = vl;
            }
    }
}

// ---------------------------------------------------------------------------
// Out kernel: CTA tile 128(n) x 128(m), K=1024 double-buffered in 64-chunks.
// grid (8, 4, 8), 256 threads (8 warps, 4x2 -> warp tile 32x64), smem 147456 B.
// ---------------------------------------------------------------------------
__global__ __launch_bounds__(256, 1) void out_mma(
    const float* __restrict__ bout, float* __restrict__ out)
{
    extern __shared__ __nv_bfloat16 sm[];
    constexpr int PB = 72;                  // padded 64-chunk stride
    constexpr int BUF = 36864;              // elems per buffer
    const int tid = threadIdx.x, wid = tid >> 5, lane = tid & 31;
    const int s = blockIdx.z, n0 = blockIdx.x * 128, m0 = blockIdx.y * 128;

    const __nv_bfloat16* gAh = g_hh + ((size_t)s * NN + n0) * FF;
    const __nv_bfloat16* gAl = g_hl + ((size_t)s * NN + n0) * FF;
    const __nv_bfloat16* gBh = g_wouth + ((size_t)s * MM + m0) * FF;
    const __nv_bfloat16* gBl = g_woutl + ((size_t)s * MM + m0) * FF;

    auto load = [&](int ch, int buf) {
        const int kc = ch * 64;
        __nv_bfloat16* base = sm + buf * BUF;
#pragma unroll
        for (int it = 0; it < 4; it++) {
            int idx = tid + it * 256;
            int row = idx >> 3, q = idx & 7;
            size_t so = (size_t)row * FF + kc + q * 8;
            int   dof = row * PB + q * 8;
            *(uint4*)(base + dof)          = *(const uint4*)(gAh + so);
            *(uint4*)(base + 9216 + dof)   = *(const uint4*)(gAl + so);
            *(uint4*)(base + 18432 + dof)  = *(const uint4*)(gBh + so);
            *(uint4*)(base + 27648 + dof)  = *(const uint4*)(gBl + so);
        }
    };

    const int wm = wid & 3, wn = wid >> 2;
    const uint32_t sb = smem_u32(sm);
    const int lrA = lane & 15, lcA = (lane >> 4) << 3;
    const int lrB = ((lane >> 4) << 3) + (lane & 7), lcB = ((lane >> 3) & 1) << 3;

    float acc[2][8][4];
#pragma unroll
    for (int mb = 0; mb < 2; mb++)
#pragma unroll
        for (int nb = 0; nb < 8; nb++)
#pragma unroll
            for (int e = 0; e < 4; e++) acc[mb][nb][e] = 0.f;

    load(0, 0);
    __syncthreads();

#pragma unroll 1
    for (int ch = 0; ch < 16; ch++) {
        const int buf = ch & 1;
        if (ch < 15) load(ch + 1, buf ^ 1);

        const uint32_t bb  = sb + (uint32_t)buf * (BUF * 2u);
        const uint32_t aAh = bb + 2 * ((wm * 32 + lrA) * PB + lcA);
        const uint32_t aAl = aAh + 2 * 9216;
        const uint32_t aBh = bb + 2 * (18432 + (wn * 64 + lrB) * PB + lcB);
        const uint32_t aBl = aBh + 2 * 9216;
#pragma unroll
        for (int kk = 0; kk < 4; kk++) {
            const int k0 = kk * 16;
            uint32_t ah[2][4], al[2][4], bh[4][4], bl[4][4];
            ldsm4(ah[0], aAh + 2 * k0);
            ldsm4(ah[1], aAh + 2 * (16 * PB + k0));
            ldsm4(al[0], aAl + 2 * k0);
            ldsm4(al[1], aAl + 2 * (16 * PB + k0));
#pragma unroll
            for (int p = 0; p < 4; p++) {
                ldsm4(bh[p], aBh + 2 * (p * 16 * PB + k0));
                ldsm4(bl[p], aBl + 2 * (p * 16 * PB + k0));
            }
#pragma unroll
            for (int mb = 0; mb < 2; mb++)
#pragma unroll
                for (int nb = 0; nb < 8; nb++) {
                    uint32_t h0 = bh[nb >> 1][(nb & 1) * 2];
                    uint32_t h1 = bh[nb >> 1][(nb & 1) * 2 + 1];
                    uint32_t l0 = bl[nb >> 1][(nb & 1) * 2];
                    uint32_t l1 = bl[nb >> 1][(nb & 1) * 2 + 1];
                    mma_bf16(acc[mb][nb], ah[mb], h0, h1);
                    mma_bf16(acc[mb][nb], ah[mb], l0, l1);
                    mma_bf16(acc[mb][nb], al[mb], h0, h1);
                }
        }
        __syncthreads();
    }

    // ---- epilogue: bias + store fp32 ----
#pragma unroll
    for (int nb = 0; nb < 8; nb++) {
        const int mc = m0 + wn * 64 + nb * 8 + (lane & 3) * 2;
        const float b0 = bout[(size_t)s * MM + mc];
        const float b1 = bout[(size_t)s * MM + mc + 1];
#pragma unroll
        for (int mb = 0; mb < 2; mb++)
#pragma unroll
            for (int hf = 0; hf < 2; hf++) {
                const int n = n0 + wm * 32 + mb * 16 + (lane >> 2) + hf * 8;
                float2 v = make_float2(acc[mb][nb][hf * 2] + b0,
                                       acc[mb][nb][hf * 2 + 1] + b1);
                *(float2*)(out + (size_t)n * (SS * MM) + s * MM + mc) = v;
            }
    }
}

// ---------------------------------------------------------------------------
// Launch. Inputs: modulation, Wxi, Whi, bi, Wxf, Whf, bf, Wxg, Whg, bg,
// Wxo, Who, bo, Wout, bout. h0 = c0 = 0 kills Whi/Wxf/Whf/bf/Whg/Who.
// ---------------------------------------------------------------------------
extern "C" void kernel_launch(void* const* d_in, const int* in_sizes, int n_in,
                              void* d_out, int out_size) {
    const float* mod  = (const float*)d_in[0];
    const float* Wxi  = (const float*)d_in[1];
    const float* bi   = (const float*)d_in[3];
    const float* Wxg  = (const float*)d_in[7];
    const float* bg   = (const float*)d_in[9];
    const float* Wxo  = (const float*)d_in[10];
    const float* bo   = (const float*)d_in[12];
    const float* Wout = (const float*)d_in[13];
    const float* bout = (const float*)d_in[14];
    float* out = (float*)d_out;

    cudaFuncSetAttribute(gates_mma, cudaFuncAttributeMaxDynamicSharedMemorySize, 174080);
    cudaFuncSetAttribute(out_mma,   cudaFuncAttributeMaxDynamicSharedMemorySize, 147456);

    convert_all<<<8192, 256>>>(mod, Wxi, Wxg, Wxo, Wout);

    dim3 gGates(NN / 128, FF / 64, SS);   // (8, 16, 8)
    gates_mma<<<gGates, 256, 174080>>>(bi, bg, bo);

    dim3 gOut(NN / 128, MM / 128, SS);    // (8, 4, 8)
    out_mma<<<gOut, 256, 147456>>>(bout, out);
}

// round 4
// speedup vs baseline: 2.5441x; 1.0797x over previous
#include <cuda_runtime.h>
#include <cuda_bf16.h>
#include <cstdint>
#include <math.h>

#define NN 1024
#define SS 8
#define II 128
#define FF 1024
#define MM 512

// ---------------------------------------------------------------------------
// Scratch (device globals; allocation-free). bf16 hi/lo split copies.
// ---------------------------------------------------------------------------
__device__ __align__(16) __nv_bfloat16 g_xh[SS * NN * II];
__device__ __align__(16) __nv_bfloat16 g_xl[SS * NN * II];
__device__ __align__(16) __nv_bfloat16 g_wih[SS * FF * II];
__device__ __align__(16) __nv_bfloat16 g_wil[SS * FF * II];
__device__ __align__(16) __nv_bfloat16 g_wgh[SS * FF * II];
__device__ __align__(16) __nv_bfloat16 g_wgl[SS * FF * II];
__device__ __align__(16) __nv_bfloat16 g_woh[SS * FF * II];
__device__ __align__(16) __nv_bfloat16 g_wol[SS * FF * II];
__device__ __align__(16) __nv_bfloat16 g_wouth[SS * MM * FF];
__device__ __align__(16) __nv_bfloat16 g_woutl[SS * MM * FF];
__device__ __align__(16) __nv_bfloat16 g_hh[SS * NN * FF];
__device__ __align__(16) __nv_bfloat16 g_hl[SS * NN * FF];

// ---------------------------------------------------------------------------
// Helpers
// ---------------------------------------------------------------------------
__device__ __forceinline__ uint32_t smem_u32(const void* p) {
    uint32_t a;
    asm("{ .reg .u64 t; cvta.to.shared.u64 t, %1; cvt.u32.u64 %0, t; }"
        : "=r"(a) : "l"(p));
    return a;
}

__device__ __forceinline__ void ldsm4(uint32_t* r, uint32_t a) {
    asm volatile("ldmatrix.sync.aligned.m8n8.x4.shared.b16 {%0,%1,%2,%3}, [%4];"
        : "=r"(r[0]), "=r"(r[1]), "=r"(r[2]), "=r"(r[3]) : "r"(a));
}

__device__ __forceinline__ void mma_bf16(float* d, const uint32_t* a,
                                         uint32_t b0, uint32_t b1) {
    asm volatile(
        "mma.sync.aligned.m16n8k16.row.col.f32.bf16.bf16.f32 "
        "{%0,%1,%2,%3}, {%4,%5,%6,%7}, {%8,%9}, {%0,%1,%2,%3};"
        : "+f"(d[0]), "+f"(d[1]), "+f"(d[2]), "+f"(d[3])
        : "r"(a[0]), "r"(a[1]), "r"(a[2]), "r"(a[3]), "r"(b0), "r"(b1));
}

__device__ __forceinline__ void cpasync16(uint32_t dst, const void* src) {
    asm volatile("cp.async.cg.shared.global [%0], [%1], 16;"
        :: "r"(dst), "l"(src));
}
#define CP_COMMIT() asm volatile("cp.async.commit_group;" ::: "memory")
#define CP_WAIT(n)  asm volatile("cp.async.wait_group %0;" :: "n"(n) : "memory")

__device__ __forceinline__ void split1(float v, __nv_bfloat16& h, __nv_bfloat16& l) {
    h = __float2bfloat16(v);
    l = __float2bfloat16(v - __bfloat162float(h));
}

// ---------------------------------------------------------------------------
// Convert: fp32 -> bf16 hi/lo. x remapped [N][S][I] -> [S][N][I].
// ---------------------------------------------------------------------------
__global__ __launch_bounds__(256) void convert_all(
    const float* __restrict__ mod, const float* __restrict__ Wxi,
    const float* __restrict__ Wxg, const float* __restrict__ Wxo,
    const float* __restrict__ Wout)
{
    const int i = blockIdx.x * 256 + threadIdx.x;
    const float* src;
    __nv_bfloat16 *dh, *dl;
    size_t soff, doff;

    if (i < 262144) {                       // x remap
        int j = i;
        int i4 = j & 31, n = (j >> 5) & 1023, s = j >> 15;
        src = mod; soff = (size_t)n * (SS * II) + s * II + i4 * 4;
        dh = g_xh; dl = g_xl; doff = ((size_t)s * NN + n) * II + i4 * 4;
    } else if (i < 524288) {                // Wxi
        size_t j = (size_t)(i - 262144) * 4;
        src = Wxi; soff = j; dh = g_wih; dl = g_wil; doff = j;
    } else if (i < 786432) {                // Wxg
        size_t j = (size_t)(i - 524288) * 4;
        src = Wxg; soff = j; dh = g_wgh; dl = g_wgl; doff = j;
    } else if (i < 1048576) {               // Wxo
        size_t j = (size_t)(i - 786432) * 4;
        src = Wxo; soff = j; dh = g_woh; dl = g_wol; doff = j;
    } else {                                // Wout
        size_t j = (size_t)(i - 1048576) * 4;
        src = Wout; soff = j; dh = g_wouth; dl = g_woutl; doff = j;
    }

    float4 v = *(const float4*)(src + soff);
    __nv_bfloat16 h[4], l[4];
    split1(v.x, h[0], l[0]);
    split1(v.y, h[1], l[1]);
    split1(v.z, h[2], l[2]);
    split1(v.w, h[3], l[3]);
    *(uint2*)(dh + doff) = *(uint2*)h;
    *(uint2*)(dl + doff) = *(uint2*)l;
}

// ---------------------------------------------------------------------------
// Gates kernel: CTA tile 128(n) x 64(f), all 3 gates, K=128 resident.
// 512 threads = 16 warps (4x4), warp tile 32(n) x 16(f) x 3 gates.
// One-shot cp.async fill. 3-term bf16-split MMA, fused LSTM epilogue.
// grid (8, 16, 8), smem 174080 B.
// ---------------------------------------------------------------------------
__global__ __launch_bounds__(512, 1) void gates_mma(
    const float* __restrict__ bi, const float* __restrict__ bg,
    const float* __restrict__ bo)
{
    extern __shared__ __nv_bfloat16 sm[];
    constexpr int PAD = 136;                // k-stride (bf16): 272 B, ldsm-clean
    const int tid = threadIdx.x, wid = tid >> 5, lane = tid & 31;
    const int s = blockIdx.z, n0 = blockIdx.x * 128, f0 = blockIdx.y * 64;
    const uint32_t sb = smem_u32(sm);

    // layout: Ah[128][PAD], Al[128][PAD], then per gate Bh[64][PAD], Bl[64][PAD]
    constexpr uint32_t OFF_AL = 128 * PAD;
    constexpr uint32_t OFF_B  = 2 * 128 * PAD;

    // ---- one-shot cp.async fill ----
    {
        const __nv_bfloat16* sh = g_xh + ((size_t)s * NN + n0) * II;
        const __nv_bfloat16* sl = g_xl + ((size_t)s * NN + n0) * II;
#pragma unroll
        for (int it = 0; it < 4; it++) {
            int idx = tid + it * 512;
            int row = idx >> 4, q = idx & 15;
            cpasync16(sb + 2 * (row * PAD + q * 8), sh + (size_t)row * II + q * 8);
            cpasync16(sb + 2 * (OFF_AL + row * PAD + q * 8),
                      sl + (size_t)row * II + q * 8);
        }
        const __nv_bfloat16* WH[3] = {g_wih, g_wgh, g_woh};
        const __nv_bfloat16* WL[3] = {g_wil, g_wgl, g_wol};
#pragma unroll
        for (int g = 0; g < 3; g++) {
            const __nv_bfloat16* bh = WH[g] + ((size_t)s * FF + f0) * II;
            const __nv_bfloat16* bl = WL[g] + ((size_t)s * FF + f0) * II;
            uint32_t dh = OFF_B + g * 2 * 64 * PAD;
#pragma unroll
            for (int it = 0; it < 2; it++) {
                int idx = tid + it * 512;
                int row = idx >> 4, q = idx & 15;
                cpasync16(sb + 2 * (dh + row * PAD + q * 8),
                          bh + (size_t)row * II + q * 8);
                cpasync16(sb + 2 * (dh + 64 * PAD + row * PAD + q * 8),
                          bl + (size_t)row * II + q * 8);
            }
        }
    }
    CP_COMMIT();
    CP_WAIT(0);
    __syncthreads();

    const int wm = wid & 3, wn = wid >> 2;
    const int lrA = lane & 15, lcA = (lane >> 4) << 3;
    const int lrB = ((lane >> 4) << 3) + (lane & 7), lcB = ((lane >> 3) & 1) << 3;

    float acc[3][2][2][4];
#pragma unroll
    for (int g = 0; g < 3; g++)
#pragma unroll
        for (int mb = 0; mb < 2; mb++)
#pragma unroll
            for (int nb = 0; nb < 2; nb++)
#pragma unroll
                for (int e = 0; e < 4; e++) acc[g][mb][nb][e] = 0.f;

    const uint32_t aAh = sb + 2 * ((wm * 32 + lrA) * PAD + lcA);
    const uint32_t aAl = aAh + 2 * OFF_AL;

#pragma unroll
    for (int kk = 0; kk < 8; kk++) {
        const int k0 = kk * 16;
        uint32_t ah[2][4], al[2][4];
        ldsm4(ah[0], aAh + 2 * k0);
        ldsm4(ah[1], aAh + 2 * (16 * PAD + k0));
        ldsm4(al[0], aAl + 2 * k0);
        ldsm4(al[1], aAl + 2 * (16 * PAD + k0));
#pragma unroll
        for (int g = 0; g < 3; g++) {
            const uint32_t bgb = sb + 2 * (OFF_B + g * 2 * 64 * PAD
                                 + (wn * 16 + lrB) * PAD + k0 + lcB);
            uint32_t bh[4], bl[4];
            ldsm4(bh, bgb);
            ldsm4(bl, bgb + 2 * (64 * PAD));
#pragma unroll
            for (int mb = 0; mb < 2; mb++)
#pragma unroll
                for (int nb = 0; nb < 2; nb++) {
                    uint32_t h0 = bh[nb * 2], h1 = bh[nb * 2 + 1];
                    uint32_t l0 = bl[nb * 2], l1 = bl[nb * 2 + 1];
                    mma_bf16(acc[g][mb][nb], ah[mb], h0, h1);
                    mma_bf16(acc[g][mb][nb], ah[mb], l0, l1);
                    mma_bf16(acc[g][mb][nb], al[mb], h0, h1);
                }
        }
    }

    // ---- fused LSTM epilogue: h = sigm(o) * tanh( sigm(i) * tanh(g) ) ----
#pragma unroll
    for (int nb = 0; nb < 2; nb++) {
        const int fc = f0 + wn * 16 + nb * 8 + (lane & 3) * 2;
        const float bi0 = bi[(size_t)s * FF + fc], bi1 = bi[(size_t)s * FF + fc + 1];
        const float bg0 = bg[(size_t)s * FF + fc], bg1 = bg[(size_t)s * FF + fc + 1];
        const float bo0 = bo[(size_t)s * FF + fc], bo1 = bo[(size_t)s * FF + fc + 1];
#pragma unroll
        for (int mb = 0; mb < 2; mb++)
#pragma unroll
            for (int hf = 0; hf < 2; hf++) {
                const int n = n0 + wm * 32 + mb * 16 + (lane >> 2) + hf * 8;
                const size_t off = ((size_t)s * NN + n) * FF + fc;
                float h2[2];
#pragma unroll
                for (int e = 0; e < 2; e++) {
                    float pi = acc[0][mb][nb][hf * 2 + e] + (e ? bi1 : bi0);
                    float pg = acc[1][mb][nb][hf * 2 + e] + (e ? bg1 : bg0);
                    float po = acc[2][mb][nb][hf * 2 + e] + (e ? bo1 : bo0);
                    float iv = 1.f / (1.f + __expf(-pi));
                    float gv = tanhf(pg);
                    float ov = 1.f / (1.f + __expf(-po));
                    h2[e] = ov * tanhf(iv * gv);
                }
                __nv_bfloat162 vh, vl;
                split1(h2[0], vh.x, vl.x);
                split1(h2[1], vh.y, vl.y);
                *(__nv_bfloat162*)(g_hh + off) = vh;
                *(__nv_bfloat162*)(g_hl + off) = vl;
            }
    }
}

// ---------------------------------------------------------------------------
// Out kernel: CTA tile 128(n) x 128(m). 512 threads = 16 warps (4x4),
// warp tile 32x32. K=1024 in 32 chunks of 32, 3-stage cp.async pipeline.
// grid (8, 4, 8), smem 122880 B.
// ---------------------------------------------------------------------------
__global__ __launch_bounds__(512, 1) void out_mma(
    const float* __restrict__ bout, float* __restrict__ out)
{
    extern __shared__ __nv_bfloat16 sm[];
    constexpr int PB = 40;                   // chunk row stride (80 B, ldsm-clean)
    constexpr uint32_t STG_B = 4u * 128 * PB * 2;   // 40960 B per stage
    constexpr uint32_t O_AL = 128 * PB * 2;         // byte offsets within stage
    constexpr uint32_t O_BH = 2u * 128 * PB * 2;
    constexpr uint32_t O_BL = 3u * 128 * PB * 2;

    const int tid = threadIdx.x, wid = tid >> 5, lane = tid & 31;
    const int s = blockIdx.z, n0 = blockIdx.x * 128, m0 = blockIdx.y * 128;
    const uint32_t sb = smem_u32(sm);

    const __nv_bfloat16* gAh = g_hh + ((size_t)s * NN + n0) * FF;
    const __nv_bfloat16* gAl = g_hl + ((size_t)s * NN + n0) * FF;
    const __nv_bfloat16* gBh = g_wouth + ((size_t)s * MM + m0) * FF;
    const __nv_bfloat16* gBl = g_woutl + ((size_t)s * MM + m0) * FF;

    const int lrow = tid >> 2, lq = tid & 3;   // 128 rows x 4 16B-chunks

    auto load = [&](int ch, int stg) {
        const int kc = ch * 32;
        const uint32_t base = sb + (uint32_t)stg * STG_B;
        const uint32_t d = 2 * (lrow * PB + lq * 8);
        const size_t so = (size_t)lrow * FF + kc + lq * 8;
        cpasync16(base + d,        gAh + so);
        cpasync16(base + O_AL + d, gAl + so);
        cpasync16(base + O_BH + d, gBh + so);
        cpasync16(base + O_BL + d, gBl + so);
    };

    const int wm = wid & 3, wn = wid >> 2;
    const int lrA = lane & 15, lcA = (lane >> 4) << 3;
    const int lrB = ((lane >> 4) << 3) + (lane & 7), lcB = ((lane >> 3) & 1) << 3;

    float acc[2][4][4];
#pragma unroll
    for (int mb = 0; mb < 2; mb++)
#pragma unroll
        for (int nb = 0; nb < 4; nb++)
#pragma unroll
            for (int e = 0; e < 4; e++) acc[mb][nb][e] = 0.f;

    load(0, 0); CP_COMMIT();
    load(1, 1); CP_COMMIT();
    load(2, 2); CP_COMMIT();

#pragma unroll 1
    for (int ch = 0; ch < 32; ch++) {
        CP_WAIT(2);
        __syncthreads();

        const int stg = ch % 3;
        const uint32_t base = sb + (uint32_t)stg * STG_B;
        const uint32_t aAh = base + 2 * ((wm * 32 + lrA) * PB + lcA);
        const uint32_t aAl = aAh + O_AL;
        const uint32_t aBh = base + O_BH + 2 * ((wn * 32 + lrB) * PB + lcB);
        const uint32_t aBl = aBh + O_AL;

#pragma unroll
        for (int kk = 0; kk < 2; kk++) {
            const int k0 = kk * 16;
            uint32_t ah[2][4], al[2][4], bh[2][4], bl[2][4];
            ldsm4(ah[0], aAh + 2 * k0);
            ldsm4(ah[1], aAh + 2 * (16 * PB + k0));
            ldsm4(al[0], aAl + 2 * k0);
            ldsm4(al[1], aAl + 2 * (16 * PB + k0));
#pragma unroll
            for (int p = 0; p < 2; p++) {
                ldsm4(bh[p], aBh + 2 * (p * 16 * PB + k0));
                ldsm4(bl[p], aBl + 2 * (p * 16 * PB + k0));
            }
#pragma unroll
            for (int mb = 0; mb < 2; mb++)
#pragma unroll
                for (int nb = 0; nb < 4; nb++) {
                    uint32_t h0 = bh[nb >> 1][(nb & 1) * 2];
                    uint32_t h1 = bh[nb >> 1][(nb & 1) * 2 + 1];
                    uint32_t l0 = bl[nb >> 1][(nb & 1) * 2];
                    uint32_t l1 = bl[nb >> 1][(nb & 1) * 2 + 1];
                    mma_bf16(acc[mb][nb], ah[mb], h0, h1);
                    mma_bf16(acc[mb][nb], ah[mb], l0, l1);
                    mma_bf16(acc[mb][nb], al[mb], h0, h1);
                }
        }
        __syncthreads();
        if (ch + 3 < 32) load(ch + 3, stg);
        CP_COMMIT();
    }

    // ---- epilogue: bias + fp32 store ----
#pragma unroll
    for (int nb = 0; nb < 4; nb++) {
        const int mc = m0 + wn * 32 + nb * 8 + (lane & 3) * 2;
        const float b0 = bout[(size_t)s * MM + mc];
        const float b1 = bout[(size_t)s * MM + mc + 1];
#pragma unroll
        for (int mb = 0; mb < 2; mb++)
#pragma unroll
            for (int hf = 0; hf < 2; hf++) {
                const int n = n0 + wm * 32 + mb * 16 + (lane >> 2) + hf * 8;
                float2 v = make_float2(acc[mb][nb][hf * 2] + b0,
                                       acc[mb][nb][hf * 2 + 1] + b1);
                *(float2*)(out + (size_t)n * (SS * MM) + s * MM + mc) = v;
            }
    }
}

// ---------------------------------------------------------------------------
// Launch. Inputs: modulation, Wxi, Whi, bi, Wxf, Whf, bf, Wxg, Whg, bg,
// Wxo, Who, bo, Wout, bout. h0 = c0 = 0 kills Whi/Wxf/Whf/bf/Whg/Who.
// ---------------------------------------------------------------------------
extern "C" void kernel_launch(void* const* d_in, const int* in_sizes, int n_in,
                              void* d_out, int out_size) {
    const float* mod  = (const float*)d_in[0];
    const float* Wxi  = (const float*)d_in[1];
    const float* bi   = (const float*)d_in[3];
    const float* Wxg  = (const float*)d_in[7];
    const float* bg   = (const float*)d_in[9];
    const float* Wxo  = (const float*)d_in[10];
    const float* bo   = (const float*)d_in[12];
    const float* Wout = (const float*)d_in[13];
    const float* bout = (const float*)d_in[14];
    float* out = (float*)d_out;

    cudaFuncSetAttribute(gates_mma, cudaFuncAttributeMaxDynamicSharedMemorySize, 174080);
    cudaFuncSetAttribute(out_mma,   cudaFuncAttributeMaxDynamicSharedMemorySize, 122880);

    convert_all<<<8192, 256>>>(mod, Wxi, Wxg, Wxo, Wout);

    dim3 gGates(NN / 128, FF / 64, SS);   // (8, 16, 8)
    gates_mma<<<gGates, 512, 174080>>>(bi, bg, bo);

    dim3 gOut(NN / 128, MM / 128, SS);    // (8, 4, 8)
    out_mma<<<gOut, 512, 122880>>>(bout, out);
}

// round 5
// speedup vs baseline: 3.4485x; 1.3555x over previous
#include <cuda_runtime.h>
#include <cuda_fp16.h>
#include <cstdint>
#include <math.h>

#define NN 1024
#define SS 8
#define II 128
#define FF 1024
#define MM 512

// ---------------------------------------------------------------------------
// Scratch (device globals). fp16; weights split hi/lo, activations unsplit.
// ---------------------------------------------------------------------------
__device__ __align__(16) __half g_xh[SS * NN * II];
__device__ __align__(16) __half g_wih[SS * FF * II];
__device__ __align__(16) __half g_wil[SS * FF * II];
__device__ __align__(16) __half g_wgh[SS * FF * II];
__device__ __align__(16) __half g_wgl[SS * FF * II];
__device__ __align__(16) __half g_woh[SS * FF * II];
__device__ __align__(16) __half g_wol[SS * FF * II];
__device__ __align__(16) __half g_wouth[SS * MM * FF];
__device__ __align__(16) __half g_woutl[SS * MM * FF];
__device__ __align__(16) __half g_hh[SS * NN * FF];

// ---------------------------------------------------------------------------
// Helpers
// ---------------------------------------------------------------------------
__device__ __forceinline__ uint32_t smem_u32(const void* p) {
    uint32_t a;
    asm("{ .reg .u64 t; cvta.to.shared.u64 t, %1; cvt.u32.u64 %0, t; }"
        : "=r"(a) : "l"(p));
    return a;
}

__device__ __forceinline__ void ldsm4(uint32_t* r, uint32_t a) {
    asm volatile("ldmatrix.sync.aligned.m8n8.x4.shared.b16 {%0,%1,%2,%3}, [%4];"
        : "=r"(r[0]), "=r"(r[1]), "=r"(r[2]), "=r"(r[3]) : "r"(a));
}

__device__ __forceinline__ void mma_f16(float* d, const uint32_t* a,
                                        uint32_t b0, uint32_t b1) {
    asm volatile(
        "mma.sync.aligned.m16n8k16.row.col.f32.f16.f16.f32 "
        "{%0,%1,%2,%3}, {%4,%5,%6,%7}, {%8,%9}, {%0,%1,%2,%3};"
        : "+f"(d[0]), "+f"(d[1]), "+f"(d[2]), "+f"(d[3])
        : "r"(a[0]), "r"(a[1]), "r"(a[2]), "r"(a[3]), "r"(b0), "r"(b1));
}

__device__ __forceinline__ void cpasync16(uint32_t dst, const void* src) {
    asm volatile("cp.async.cg.shared.global [%0], [%1], 16;"
        :: "r"(dst), "l"(src));
}
#define CP_COMMIT() asm volatile("cp.async.commit_group;" ::: "memory")
#define CP_WAIT(n)  asm volatile("cp.async.wait_group %0;" :: "n"(n) : "memory")

__device__ __forceinline__ void split1h(float v, __half& h, __half& l) {
    h = __float2half_rn(v);
    l = __float2half_rn(v - __half2float(h));
}

// ---------------------------------------------------------------------------
// Convert: fp32 -> fp16. x remapped [N][S][I] -> [S][N][I] (hi only);
// weights (Wxi/Wxg/Wxo/Wout) split hi/lo.
// ---------------------------------------------------------------------------
__global__ __launch_bounds__(256) void convert_all(
    const float* __restrict__ mod, const float* __restrict__ Wxi,
    const float* __restrict__ Wxg, const float* __restrict__ Wxo,
    const float* __restrict__ Wout)
{
    const int i = blockIdx.x * 256 + threadIdx.x;
    if (i < 262144) {                       // x remap, hi only
        int i4 = i & 31, n = (i >> 5) & 1023, s = i >> 15;
        float4 v = *(const float4*)(mod + (size_t)n * (SS * II) + s * II + i4 * 4);
        __half h[4] = {__float2half_rn(v.x), __float2half_rn(v.y),
                       __float2half_rn(v.z), __float2half_rn(v.w)};
        *(uint2*)(g_xh + ((size_t)s * NN + n) * II + i4 * 4) = *(uint2*)h;
        return;
    }
    const float* src;
    __half *dh, *dl;
    size_t j;
    if (i < 524288)       { j = (size_t)(i - 262144) * 4;  src = Wxi;  dh = g_wih;   dl = g_wil; }
    else if (i < 786432)  { j = (size_t)(i - 524288) * 4;  src = Wxg;  dh = g_wgh;   dl = g_wgl; }
    else if (i < 1048576) { j = (size_t)(i - 786432) * 4;  src = Wxo;  dh = g_woh;   dl = g_wol; }
    else                  { j = (size_t)(i - 1048576) * 4; src = Wout; dh = g_wouth; dl = g_woutl; }

    float4 v = *(const float4*)(src + j);
    __half h[4], l[4];
    split1h(v.x, h[0], l[0]);
    split1h(v.y, h[1], l[1]);
    split1h(v.z, h[2], l[2]);
    split1h(v.w, h[3], l[3]);
    *(uint2*)(dh + j) = *(uint2*)h;
    *(uint2*)(dl + j) = *(uint2*)l;
}

// ---------------------------------------------------------------------------
// Gates kernel: CTA tile 128(n) x 64(f), all 3 gates, K=128 resident.
// 512 threads = 16 warps (4x4), warp tile 32(n) x 16(f).
// fp16 2-term MMA (Ah*Bh + Ah*Bl). Fused LSTM epilogue -> h fp16.
// grid (8, 16, 8), smem 139264 B.
// ---------------------------------------------------------------------------
__global__ __launch_bounds__(512, 1) void gates_mma(
    const float* __restrict__ bi, const float* __restrict__ bg,
    const float* __restrict__ bo)
{
    extern __shared__ __half sm[];
    constexpr int PAD = 136;                 // k-stride (fp16): 272 B, ldsm-clean
    constexpr uint32_t OFF_B = 128 * PAD;    // A[128][PAD], then per gate hi/lo
    const int tid = threadIdx.x, wid = tid >> 5, lane = tid & 31;
    const int s = blockIdx.z, n0 = blockIdx.x * 128, f0 = blockIdx.y * 64;
    const uint32_t sb = smem_u32(sm);

    // ---- one-shot cp.async fill ----
    {
        const __half* sa = g_xh + ((size_t)s * NN + n0) * II;
#pragma unroll
        for (int it = 0; it < 4; it++) {
            int idx = tid + it * 512;
            int row = idx >> 4, q = idx & 15;
            cpasync16(sb + 2 * (row * PAD + q * 8), sa + (size_t)row * II + q * 8);
        }
        const __half* WH[3] = {g_wih, g_wgh, g_woh};
        const __half* WL[3] = {g_wil, g_wgl, g_wol};
#pragma unroll
        for (int g = 0; g < 3; g++) {
            const __half* bh = WH[g] + ((size_t)s * FF + f0) * II;
            const __half* bl = WL[g] + ((size_t)s * FF + f0) * II;
            uint32_t dh = OFF_B + g * 2 * 64 * PAD;
#pragma unroll
            for (int it = 0; it < 2; it++) {
                int idx = tid + it * 512;
                int row = idx >> 4, q = idx & 15;
                cpasync16(sb + 2 * (dh + row * PAD + q * 8),
                          bh + (size_t)row * II + q * 8);
                cpasync16(sb + 2 * (dh + 64 * PAD + row * PAD + q * 8),
                          bl + (size_t)row * II + q * 8);
            }
        }
    }
    CP_COMMIT();
    CP_WAIT(0);
    __syncthreads();

    const int wm = wid & 3, wn = wid >> 2;
    const int lrA = lane & 15, lcA = (lane >> 4) << 3;
    const int lrB = ((lane >> 4) << 3) + (lane & 7), lcB = ((lane >> 3) & 1) << 3;

    float acc[3][2][2][4];
#pragma unroll
    for (int g = 0; g < 3; g++)
#pragma unroll
        for (int mb = 0; mb < 2; mb++)
#pragma unroll
            for (int nb = 0; nb < 2; nb++)
#pragma unroll
                for (int e = 0; e < 4; e++) acc[g][mb][nb][e] = 0.f;

    const uint32_t aAh = sb + 2 * ((wm * 32 + lrA) * PAD + lcA);

#pragma unroll
    for (int kk = 0; kk < 8; kk++) {
        const int k0 = kk * 16;
        uint32_t ah[2][4];
        ldsm4(ah[0], aAh + 2 * k0);
        ldsm4(ah[1], aAh + 2 * (16 * PAD + k0));
#pragma unroll
        for (int g = 0; g < 3; g++) {
            const uint32_t bgb = sb + 2 * (OFF_B + g * 2 * 64 * PAD
                                 + (wn * 16 + lrB) * PAD + k0 + lcB);
            uint32_t bh[4], bl[4];
            ldsm4(bh, bgb);
            ldsm4(bl, bgb + 2 * (64 * PAD));
#pragma unroll
            for (int mb = 0; mb < 2; mb++)
#pragma unroll
                for (int nb = 0; nb < 2; nb++) {
                    mma_f16(acc[g][mb][nb], ah[mb], bh[nb * 2], bh[nb * 2 + 1]);
                    mma_f16(acc[g][mb][nb], ah[mb], bl[nb * 2], bl[nb * 2 + 1]);
                }
        }
    }

    // ---- fused LSTM epilogue: h = sigm(o) * tanh( sigm(i) * tanh(g) ) ----
#pragma unroll
    for (int nb = 0; nb < 2; nb++) {
        const int fc = f0 + wn * 16 + nb * 8 + (lane & 3) * 2;
        const float bi0 = bi[(size_t)s * FF + fc], bi1 = bi[(size_t)s * FF + fc + 1];
        const float bg0 = bg[(size_t)s * FF + fc], bg1 = bg[(size_t)s * FF + fc + 1];
        const float bo0 = bo[(size_t)s * FF + fc], bo1 = bo[(size_t)s * FF + fc + 1];
#pragma unroll
        for (int mb = 0; mb < 2; mb++)
#pragma unroll
            for (int hf = 0; hf < 2; hf++) {
                const int n = n0 + wm * 32 + mb * 16 + (lane >> 2) + hf * 8;
                const size_t off = ((size_t)s * NN + n) * FF + fc;
                float h2[2];
#pragma unroll
                for (int e = 0; e < 2; e++) {
                    float pi = acc[0][mb][nb][hf * 2 + e] + (e ? bi1 : bi0);
                    float pg = acc[1][mb][nb][hf * 2 + e] + (e ? bg1 : bg0);
                    float po = acc[2][mb][nb][hf * 2 + e] + (e ? bo1 : bo0);
                    float iv = 1.f / (1.f + __expf(-pi));
                    float gv = tanhf(pg);
                    float ov = 1.f / (1.f + __expf(-po));
                    h2[e] = ov * tanhf(iv * gv);
                }
                *(__half2*)(g_hh + off) = __floats2half2_rn(h2[0], h2[1]);
            }
    }
}

// ---------------------------------------------------------------------------
// Out kernel: CTA tile 128(n) x 128(m). 256 threads = 8 warps (2x4),
// warp tile 64(n) x 32(m). K=1024 in 32 chunks of 32, 3-stage cp.async.
// 2 CTAs/SM (smem 92160 B, <=128 regs). grid (8, 4, 8) -> single wave.
// ---------------------------------------------------------------------------
__global__ __launch_bounds__(256, 2) void out_mma(
    const float* __restrict__ bout, float* __restrict__ out)
{
    extern __shared__ __half sm[];
    constexpr int PB = 40;                         // row stride (80 B, ldsm-clean)
    constexpr uint32_t TEN = 128 * PB;             // elems per tensor per stage
    constexpr uint32_t STG_B = 3u * TEN * 2;       // 30720 B per stage

    const int tid = threadIdx.x, wid = tid >> 5, lane = tid & 31;
    const int s = blockIdx.z, n0 = blockIdx.x * 128, m0 = blockIdx.y * 128;
    const uint32_t sb = smem_u32(sm);

    const __half* gA  = g_hh    + ((size_t)s * NN + n0) * FF;
    const __half* gBh = g_wouth + ((size_t)s * MM + m0) * FF;
    const __half* gBl = g_woutl + ((size_t)s * MM + m0) * FF;

    auto load = [&](int ch, int stg) {
        const int kc = ch * 32;
        const uint32_t base = sb + (uint32_t)stg * STG_B;
#pragma unroll
        for (int it = 0; it < 2; it++) {
            int idx = tid + it * 256;
            int row = idx >> 2, q = idx & 3;
            const uint32_t d = 2 * (row * PB + q * 8);
            const size_t so = (size_t)row * FF + kc + q * 8;
            cpasync16(base + d,               gA  + so);
            cpasync16(base + 2 * TEN + d,     gBh + so);
            cpasync16(base + 2 * 2 * TEN + d, gBl + so);
        }
    };

    const int wm = wid & 1, wn = wid >> 1;
    const int lrA = lane & 15, lcA = (lane >> 4) << 3;
    const int lrB = ((lane >> 4) << 3) + (lane & 7), lcB = ((lane >> 3) & 1) << 3;

    float acc[4][4][4];
#pragma unroll
    for (int mb = 0; mb < 4; mb++)
#pragma unroll
        for (int nb = 0; nb < 4; nb++)
#pragma unroll
            for (int e = 0; e < 4; e++) acc[mb][nb][e] = 0.f;

    load(0, 0); CP_COMMIT();
    load(1, 1); CP_COMMIT();
    load(2, 2); CP_COMMIT();

#pragma unroll 1
    for (int ch = 0; ch < 32; ch++) {
        CP_WAIT(2);
        __syncthreads();

        const int stg = ch % 3;
        const uint32_t base = sb + (uint32_t)stg * STG_B;
        const uint32_t aA  = base + 2 * ((wm * 64 + lrA) * PB + lcA);
        const uint32_t aBh = base + 2 * (TEN + (wn * 32 + lrB) * PB + lcB);
        const uint32_t aBl = aBh + 2 * TEN;

#pragma unroll
        for (int kk = 0; kk < 2; kk++) {
            const int k0 = kk * 16;
            uint32_t ah[4][4], bh[2][4], bl[2][4];
#pragma unroll
            for (int mb = 0; mb < 4; mb++)
                ldsm4(ah[mb], aA + 2 * (mb * 16 * PB + k0));
#pragma unroll
            for (int p = 0; p < 2; p++) {
                ldsm4(bh[p], aBh + 2 * (p * 16 * PB + k0));
                ldsm4(bl[p], aBl + 2 * (p * 16 * PB + k0));
            }
#pragma unroll
            for (int mb = 0; mb < 4; mb++)
#pragma unroll
                for (int nb = 0; nb < 4; nb++) {
                    uint32_t h0 = bh[nb >> 1][(nb & 1) * 2];
                    uint32_t h1 = bh[nb >> 1][(nb & 1) * 2 + 1];
                    uint32_t l0 = bl[nb >> 1][(nb & 1) * 2];
                    uint32_t l1 = bl[nb >> 1][(nb & 1) * 2 + 1];
                    mma_f16(acc[mb][nb], ah[mb], h0, h1);
                    mma_f16(acc[mb][nb], ah[mb], l0, l1);
                }
        }
        __syncthreads();
        if (ch + 3 < 32) load(ch + 3, stg);
        CP_COMMIT();
    }

    // ---- epilogue: bias + fp32 store ----
#pragma unroll
    for (int nb = 0; nb < 4; nb++) {
        const int mc = m0 + wn * 32 + nb * 8 + (lane & 3) * 2;
        const float b0 = bout[(size_t)s * MM + mc];
        const float b1 = bout[(size_t)s * MM + mc + 1];
#pragma unroll
        for (int mb = 0; mb < 4; mb++)
#pragma unroll
            for (int hf = 0; hf < 2; hf++) {
                const int n = n0 + wm * 64 + mb * 16 + (lane >> 2) + hf * 8;
                float2 v = make_float2(acc[mb][nb][hf * 2] + b0,
                                       acc[mb][nb][hf * 2 + 1] + b1);
                *(float2*)(out + (size_t)n * (SS * MM) + s * MM + mc) = v;
            }
    }
}

// ---------------------------------------------------------------------------
// Launch. Inputs: modulation, Wxi, Whi, bi, Wxf, Whf, bf, Wxg, Whg, bg,
// Wxo, Who, bo, Wout, bout. h0 = c0 = 0 kills Whi/Wxf/Whf/bf/Whg/Who.
// ---------------------------------------------------------------------------
extern "C" void kernel_launch(void* const* d_in, const int* in_sizes, int n_in,
                              void* d_out, int out_size) {
    const float* mod  = (const float*)d_in[0];
    const float* Wxi  = (const float*)d_in[1];
    const float* bi   = (const float*)d_in[3];
    const float* Wxg  = (const float*)d_in[7];
    const float* bg   = (const float*)d_in[9];
    const float* Wxo  = (const float*)d_in[10];
    const float* bo   = (const float*)d_in[12];
    const float* Wout = (const float*)d_in[13];
    const float* bout = (const float*)d_in[14];
    float* out = (float*)d_out;

    cudaFuncSetAttribute(gates_mma, cudaFuncAttributeMaxDynamicSharedMemorySize, 139264);
    cudaFuncSetAttribute(out_mma,   cudaFuncAttributeMaxDynamicSharedMemorySize, 92160);

    convert_all<<<8192, 256>>>(mod, Wxi, Wxg, Wxo, Wout);

    dim3 gGates(NN / 128, FF / 64, SS);   // (8, 16, 8)
    gates_mma<<<gGates, 512, 139264>>>(bi, bg, bo);

    dim3 gOut(NN / 128, MM / 128, SS);    // (8, 4, 8)
    out_mma<<<gOut, 256, 92160>>>(bout, out);
}

// round 6
// speedup vs baseline: 4.8995x; 1.4208x over previous
#include <cuda_runtime.h>
#include <cuda_fp16.h>
#include <cstdint>
#include <math.h>

#define NN 1024
#define SS 8
#define II 128
#define FF 1024
#define MM 512

// ---------------------------------------------------------------------------
// Scratch (device globals). Pure fp16, single term.
// ---------------------------------------------------------------------------
__device__ __align__(16) __half g_xh[SS * NN * II];
__device__ __align__(16) __half g_wih[SS * FF * II];
__device__ __align__(16) __half g_wgh[SS * FF * II];
__device__ __align__(16) __half g_woh[SS * FF * II];
__device__ __align__(16) __half g_wouth[SS * MM * FF];
__device__ __align__(16) __half g_hh[SS * NN * FF];

// ---------------------------------------------------------------------------
// Helpers
// ---------------------------------------------------------------------------
__device__ __forceinline__ uint32_t smem_u32(const void* p) {
    uint32_t a;
    asm("{ .reg .u64 t; cvta.to.shared.u64 t, %1; cvt.u32.u64 %0, t; }"
        : "=r"(a) : "l"(p));
    return a;
}

__device__ __forceinline__ void ldsm4(uint32_t* r, uint32_t a) {
    asm volatile("ldmatrix.sync.aligned.m8n8.x4.shared.b16 {%0,%1,%2,%3}, [%4];"
        : "=r"(r[0]), "=r"(r[1]), "=r"(r[2]), "=r"(r[3]) : "r"(a));
}

__device__ __forceinline__ void mma_f16(float* d, const uint32_t* a,
                                        uint32_t b0, uint32_t b1) {
    asm volatile(
        "mma.sync.aligned.m16n8k16.row.col.f32.f16.f16.f32 "
        "{%0,%1,%2,%3}, {%4,%5,%6,%7}, {%8,%9}, {%0,%1,%2,%3};"
        : "+f"(d[0]), "+f"(d[1]), "+f"(d[2]), "+f"(d[3])
        : "r"(a[0]), "r"(a[1]), "r"(a[2]), "r"(a[3]), "r"(b0), "r"(b1));
}

__device__ __forceinline__ void cpasync16(uint32_t dst, const void* src) {
    asm volatile("cp.async.cg.shared.global [%0], [%1], 16;"
        :: "r"(dst), "l"(src));
}
#define CP_COMMIT() asm volatile("cp.async.commit_group;" ::: "memory")
#define CP_WAIT(n)  asm volatile("cp.async.wait_group %0;" :: "n"(n) : "memory")

// ---------------------------------------------------------------------------
// Convert: fp32 -> fp16 (round-to-nearest). x remapped [N][S][I] -> [S][N][I].
// ---------------------------------------------------------------------------
__global__ __launch_bounds__(256) void convert_all(
    const float* __restrict__ mod, const float* __restrict__ Wxi,
    const float* __restrict__ Wxg, const float* __restrict__ Wxo,
    const float* __restrict__ Wout)
{
    const int i = blockIdx.x * 256 + threadIdx.x;
    if (i < 262144) {                       // x remap
        int i4 = i & 31, n = (i >> 5) & 1023, s = i >> 15;
        float4 v = *(const float4*)(mod + (size_t)n * (SS * II) + s * II + i4 * 4);
        __half h[4] = {__float2half_rn(v.x), __float2half_rn(v.y),
                       __float2half_rn(v.z), __float2half_rn(v.w)};
        *(uint2*)(g_xh + ((size_t)s * NN + n) * II + i4 * 4) = *(uint2*)h;
        return;
    }
    const float* src;
    __half* dh;
    size_t j;
    if (i < 524288)       { j = (size_t)(i - 262144) * 4;  src = Wxi;  dh = g_wih; }
    else if (i < 786432)  { j = (size_t)(i - 524288) * 4;  src = Wxg;  dh = g_wgh; }
    else if (i < 1048576) { j = (size_t)(i - 786432) * 4;  src = Wxo;  dh = g_woh; }
    else                  { j = (size_t)(i - 1048576) * 4; src = Wout; dh = g_wouth; }

    float4 v = *(const float4*)(src + j);
    __half h[4] = {__float2half_rn(v.x), __float2half_rn(v.y),
                   __float2half_rn(v.z), __float2half_rn(v.w)};
    *(uint2*)(dh + j) = *(uint2*)h;
}

// ---------------------------------------------------------------------------
// Gates kernel: CTA tile 128(n) x 64(f), all 3 gates, K=128 resident.
// 512 threads = 16 warps (4x4), warp tile 32(n) x 16(f). Single-term fp16.
// Fused LSTM epilogue -> h fp16. grid (8, 16, 8), smem 87040 B.
// ---------------------------------------------------------------------------
__global__ __launch_bounds__(512, 1) void gates_mma(
    const float* __restrict__ bi, const float* __restrict__ bg,
    const float* __restrict__ bo)
{
    extern __shared__ __half sm[];
    constexpr int PAD = 136;                 // k-stride (fp16): 272 B, ldsm-clean
    constexpr uint32_t OFF_B = 128 * PAD;    // A[128][PAD], then per-gate B[64][PAD]
    const int tid = threadIdx.x, wid = tid >> 5, lane = tid & 31;
    const int s = blockIdx.z, n0 = blockIdx.x * 128, f0 = blockIdx.y * 64;
    const uint32_t sb = smem_u32(sm);

    // ---- one-shot cp.async fill ----
    {
        const __half* sa = g_xh + ((size_t)s * NN + n0) * II;
#pragma unroll
        for (int it = 0; it < 4; it++) {
            int idx = tid + it * 512;
            int row = idx >> 4, q = idx & 15;
            cpasync16(sb + 2 * (row * PAD + q * 8), sa + (size_t)row * II + q * 8);
        }
        const __half* WH[3] = {g_wih, g_wgh, g_woh};
#pragma unroll
        for (int g = 0; g < 3; g++) {
            const __half* bh = WH[g] + ((size_t)s * FF + f0) * II;
            uint32_t dh = OFF_B + g * 64 * PAD;
#pragma unroll
            for (int it = 0; it < 2; it++) {
                int idx = tid + it * 512;
                int row = idx >> 4, q = idx & 15;
                cpasync16(sb + 2 * (dh + row * PAD + q * 8),
                          bh + (size_t)row * II + q * 8);
            }
        }
    }
    CP_COMMIT();
    CP_WAIT(0);
    __syncthreads();

    const int wm = wid & 3, wn = wid >> 2;
    const int lrA = lane & 15, lcA = (lane >> 4) << 3;
    const int lrB = ((lane >> 4) << 3) + (lane & 7), lcB = ((lane >> 3) & 1) << 3;

    float acc[3][2][2][4];
#pragma unroll
    for (int g = 0; g < 3; g++)
#pragma unroll
        for (int mb = 0; mb < 2; mb++)
#pragma unroll
            for (int nb = 0; nb < 2; nb++)
#pragma unroll
                for (int e = 0; e < 4; e++) acc[g][mb][nb][e] = 0.f;

    const uint32_t aAh = sb + 2 * ((wm * 32 + lrA) * PAD + lcA);

#pragma unroll
    for (int kk = 0; kk < 8; kk++) {
        const int k0 = kk * 16;
        uint32_t ah[2][4];
        ldsm4(ah[0], aAh + 2 * k0);
        ldsm4(ah[1], aAh + 2 * (16 * PAD + k0));
#pragma unroll
        for (int g = 0; g < 3; g++) {
            const uint32_t bgb = sb + 2 * (OFF_B + g * 64 * PAD
                                 + (wn * 16 + lrB) * PAD + k0 + lcB);
            uint32_t bh[4];
            ldsm4(bh, bgb);
#pragma unroll
            for (int mb = 0; mb < 2; mb++)
#pragma unroll
                for (int nb = 0; nb < 2; nb++)
                    mma_f16(acc[g][mb][nb], ah[mb], bh[nb * 2], bh[nb * 2 + 1]);
        }
    }

    // ---- fused LSTM epilogue: h = sigm(o) * tanh( sigm(i) * tanh(g) ) ----
#pragma unroll
    for (int nb = 0; nb < 2; nb++) {
        const int fc = f0 + wn * 16 + nb * 8 + (lane & 3) * 2;
        const float bi0 = bi[(size_t)s * FF + fc], bi1 = bi[(size_t)s * FF + fc + 1];
        const float bg0 = bg[(size_t)s * FF + fc], bg1 = bg[(size_t)s * FF + fc + 1];
        const float bo0 = bo[(size_t)s * FF + fc], bo1 = bo[(size_t)s * FF + fc + 1];
#pragma unroll
        for (int mb = 0; mb < 2; mb++)
#pragma unroll
            for (int hf = 0; hf < 2; hf++) {
                const int n = n0 + wm * 32 + mb * 16 + (lane >> 2) + hf * 8;
                const size_t off = ((size_t)s * NN + n) * FF + fc;
                float h2[2];
#pragma unroll
                for (int e = 0; e < 2; e++) {
                    float pi = acc[0][mb][nb][hf * 2 + e] + (e ? bi1 : bi0);
                    float pg = acc[1][mb][nb][hf * 2 + e] + (e ? bg1 : bg0);
                    float po = acc[2][mb][nb][hf * 2 + e] + (e ? bo1 : bo0);
                    float iv = 1.f / (1.f + __expf(-pi));
                    float gv = tanhf(pg);
                    float ov = 1.f / (1.f + __expf(-po));
                    h2[e] = ov * tanhf(iv * gv);
                }
                *(__half2*)(g_hh + off) = __floats2half2_rn(h2[0], h2[1]);
            }
    }
}

// ---------------------------------------------------------------------------
// Out kernel: CTA tile 128(n) x 128(m). 256 threads = 8 warps (2x4),
// warp tile 64(n) x 32(m). K=1024 in 32 chunks of 32, 3-stage cp.async.
// Single-term fp16. 2 CTAs/SM (smem 61440 B). grid (8, 4, 8).
// ---------------------------------------------------------------------------
__global__ __launch_bounds__(256, 2) void out_mma(
    const float* __restrict__ bout, float* __restrict__ out)
{
    extern __shared__ __half sm[];
    constexpr int PB = 40;                         // row stride (80 B, ldsm-clean)
    constexpr uint32_t TEN = 128 * PB;             // elems per tensor per stage
    constexpr uint32_t STG_B = 2u * TEN * 2;       // 20480 B per stage

    const int tid = threadIdx.x, wid = tid >> 5, lane = tid & 31;
    const int s = blockIdx.z, n0 = blockIdx.x * 128, m0 = blockIdx.y * 128;
    const uint32_t sb = smem_u32(sm);

    const __half* gA = g_hh    + ((size_t)s * NN + n0) * FF;
    const __half* gB = g_wouth + ((size_t)s * MM + m0) * FF;

    auto load = [&](int ch, int stg) {
        const int kc = ch * 32;
        const uint32_t base = sb + (uint32_t)stg * STG_B;
#pragma unroll
        for (int it = 0; it < 2; it++) {
            int idx = tid + it * 256;
            int row = idx >> 2, q = idx & 3;
            const uint32_t d = 2 * (row * PB + q * 8);
            const size_t so = (size_t)row * FF + kc + q * 8;
            cpasync16(base + d,           gA + so);
            cpasync16(base + 2 * TEN + d, gB + so);
        }
    };

    const int wm = wid & 1, wn = wid >> 1;
    const int lrA = lane & 15, lcA = (lane >> 4) << 3;
    const int lrB = ((lane >> 4) << 3) + (lane & 7), lcB = ((lane >> 3) & 1) << 3;

    float acc[4][4][4];
#pragma unroll
    for (int mb = 0; mb < 4; mb++)
#pragma unroll
        for (int nb = 0; nb < 4; nb++)
#pragma unroll
            for (int e = 0; e < 4; e++) acc[mb][nb][e] = 0.f;

    load(0, 0); CP_COMMIT();
    load(1, 1); CP_COMMIT();
    load(2, 2); CP_COMMIT();

#pragma unroll 1
    for (int ch = 0; ch < 32; ch++) {
        CP_WAIT(2);
        __syncthreads();

        const int stg = ch % 3;
        const uint32_t base = sb + (uint32_t)stg * STG_B;
        const uint32_t aA = base + 2 * ((wm * 64 + lrA) * PB + lcA);
        const uint32_t aB = base + 2 * (TEN + (wn * 32 + lrB) * PB + lcB);

#pragma unroll
        for (int kk = 0; kk < 2; kk++) {
            const int k0 = kk * 16;
            uint32_t ah[4][4], bh[2][4];
#pragma unroll
            for (int mb = 0; mb < 4; mb++)
                ldsm4(ah[mb], aA + 2 * (mb * 16 * PB + k0));
#pragma unroll
            for (int p = 0; p < 2; p++)
                ldsm4(bh[p], aB + 2 * (p * 16 * PB + k0));
#pragma unroll
            for (int mb = 0; mb < 4; mb++)
#pragma unroll
                for (int nb = 0; nb < 4; nb++)
                    mma_f16(acc[mb][nb], ah[mb],
                            bh[nb >> 1][(nb & 1) * 2], bh[nb >> 1][(nb & 1) * 2 + 1]);
        }
        __syncthreads();
        if (ch + 3 < 32) load(ch + 3, stg);
        CP_COMMIT();
    }

    // ---- epilogue: bias + fp32 store ----
#pragma unroll
    for (int nb = 0; nb < 4; nb++) {
        const int mc = m0 + wn * 32 + nb * 8 + (lane & 3) * 2;
        const float b0 = bout[(size_t)s * MM + mc];
        const float b1 = bout[(size_t)s * MM + mc + 1];
#pragma unroll
        for (int mb = 0; mb < 4; mb++)
#pragma unroll
            for (int hf = 0; hf < 2; hf++) {
                const int n = n0 + wm * 64 + mb * 16 + (lane >> 2) + hf * 8;
                float2 v = make_float2(acc[mb][nb][hf * 2] + b0,
                                       acc[mb][nb][hf * 2 + 1] + b1);
                *(float2*)(out + (size_t)n * (SS * MM) + s * MM + mc) = v;
            }
    }
}

// ---------------------------------------------------------------------------
// Launch. Inputs: modulation, Wxi, Whi, bi, Wxf, Whf, bf, Wxg, Whg, bg,
// Wxo, Who, bo, Wout, bout. h0 = c0 = 0 kills Whi/Wxf/Whf/bf/Whg/Who.
// ---------------------------------------------------------------------------
extern "C" void kernel_launch(void* const* d_in, const int* in_sizes, int n_in,
                              void* d_out, int out_size) {
    const float* mod  = (const float*)d_in[0];
    const float* Wxi  = (const float*)d_in[1];
    const float* bi   = (const float*)d_in[3];
    const float* Wxg  = (const float*)d_in[7];
    const float* bg   = (const float*)d_in[9];
    const float* Wxo  = (const float*)d_in[10];
    const float* bo   = (const float*)d_in[12];
    const float* Wout = (const float*)d_in[13];
    const float* bout = (const float*)d_in[14];
    float* out = (float*)d_out;

    cudaFuncSetAttribute(gates_mma, cudaFuncAttributeMaxDynamicSharedMemorySize, 87040);
    cudaFuncSetAttribute(out_mma,   cudaFuncAttributeMaxDynamicSharedMemorySize, 61440);

    convert_all<<<8192, 256>>>(mod, Wxi, Wxg, Wxo, Wout);

    dim3 gGates(NN / 128, FF / 64, SS);   // (8, 16, 8)
    gates_mma<<<gGates, 512, 87040>>>(bi, bg, bo);

    dim3 gOut(NN / 128, MM / 128, SS);    // (8, 4, 8)
    out_mma<<<gOut, 256, 61440>>>(bout, out);
}